// round 16
// baseline (speedup 1.0000x reference)
#include <cuda_runtime.h>
#include <cooperative_groups.h>
#include <math.h>

namespace cg = cooperative_groups;

#define BB 16
#define SS 2048
#define DD 768
#define DD4 192          // DD/4
#define KW 3
#define ROW3 (DD*KW)     // 2304
#define CH 8             // scan chunks per batch = cluster size
#define CSZ (SS/CH)      // 256 steps per chunk
#define TPB_A 32         // t-values per kA block
#define OG 8             // o-groups per kA block
#define OPG (DD/OG)      // 96 o's per group
#define JG 8             // output rows per kD block

// ---- scratch (no allocations allowed; .bss-zeroed at load) ----
__device__ float  g_weff[KW][DD];     // w_eff[k][d], d contiguous
__device__ float  g_beff;
__device__ float4 g_rx[BB*SS];        // shifted stencil: slot t = (r0[t-1], r1[t], r2[t+1], -)
__device__ float  g_wmain[BB*SS];
__device__ float  g_wspill[BB*SS];
__device__ int    g_firepos[BB*SS];   // per batch: step index of fire j
__device__ int    g_F[BB];            // number of fires per batch

// ============================================================
// kA: fused w_eff + b_eff, ONE launch, no cross-block combine.
// grid 72 x 256.  Block bi owns t in [bi*32, bi*32+32).
// ============================================================
__global__ void kA(const float* __restrict__ conv_w,
                   const float* __restrict__ conv_b,
                   const float* __restrict__ lin_w,
                   const float* __restrict__ lin_b) {
    __shared__ float sp[OG][TPB_A];
    int tl = threadIdx.x & 31;         // t_local
    int g  = threadIdx.x >> 5;         // o-group
    int t  = blockIdx.x * TPB_A + tl;  // 0..2303

    float acc = 0.f;
    int o0 = g * OPG;
#pragma unroll 8
    for (int o = o0; o < o0 + OPG; ++o)
        acc += __ldg(lin_w + o) * conv_w[o * ROW3 + t];
    sp[g][tl] = acc;
    __syncthreads();

    if (g == 0) {                      // fixed-order combine (deterministic)
        float s = 0.f;
#pragma unroll
        for (int gg = 0; gg < OG; ++gg) s += sp[gg][tl];
        g_weff[t % 3][t / 3] = s;
    }

    if (blockIdx.x == 0) {             // b_eff = lin_w . conv_b + lin_b
        __shared__ float red[256];
        float s2 = 0.f;
        for (int i = threadIdx.x; i < DD; i += 256)
            s2 += lin_w[i] * conv_b[i];
        red[threadIdx.x] = s2;
        __syncthreads();
        for (int st = 128; st > 0; st >>= 1) {
            if (threadIdx.x < st) red[threadIdx.x] += red[threadIdx.x + st];
            __syncthreads();
        }
        if (threadIdx.x == 0) g_beff = red[0] + lin_b[0];
    }
}

// ============================================================
// kB: r_k[b,t] = sum_d w_eff[d,k] * x[b,t,d].  One warp per row.
// Writes shifted slots: slot t .x = r0[t-1], .y = r1[t], .z = r2[t+1].
// Rows with t > len[b] dead -> early-out (slots stay 0; lens replay-const).
// grid BB*SS/8 x 256
// ============================================================
__global__ void kB(const float* __restrict__ x, const int* __restrict__ lens) {
    int row  = blockIdx.x * 8 + (threadIdx.x >> 5);   // 0..BB*SS-1
    int lane = threadIdx.x & 31;
    int b = row >> 11;                 // row / SS
    int t = row & (SS - 1);
    if (t > __ldg(lens + b)) return;

    const float4* xr = (const float4*)(x) + (size_t)row * DD4;
    const float4* w0 = (const float4*)g_weff[0];
    const float4* w1 = (const float4*)g_weff[1];
    const float4* w2 = (const float4*)g_weff[2];
    float a0 = 0.f, a1 = 0.f, a2 = 0.f;
#pragma unroll
    for (int i = 0; i < 6; ++i) {
        int c = lane + i * 32;
        float4 xv = xr[c];
        float4 v0 = w0[c], v1 = w1[c], v2 = w2[c];
        a0 += xv.x*v0.x + xv.y*v0.y + xv.z*v0.z + xv.w*v0.w;
        a1 += xv.x*v1.x + xv.y*v1.y + xv.z*v1.z + xv.w*v1.w;
        a2 += xv.x*v2.x + xv.y*v2.y + xv.z*v2.z + xv.w*v2.w;
    }
#pragma unroll
    for (int off = 16; off > 0; off >>= 1) {
        a0 += __shfl_down_sync(0xffffffffu, a0, off);
        a1 += __shfl_down_sync(0xffffffffu, a1, off);
        a2 += __shfl_down_sync(0xffffffffu, a2, off);
    }
    if (lane == 0) {
        g_rx[row].y = a1;                        // r1[t] -> slot t
        if (t + 1 < SS) g_rx[row + 1].x = a0;    // r0[t] -> slot t+1
        if (t > 0)      g_rx[row - 1].z = a2;    // r2[t] -> slot t-1
    }
}

// ============================================================
// kCc: fused clustered scan.  grid BB*CH x 256, cluster (8,1,1).
// ============================================================
__global__ void __cluster_dims__(CH, 1, 1)
kCc(const int* __restrict__ lens, float* __restrict__ lens_out) {
    __shared__ double wt[8], wo[8];
    __shared__ double ctot[CH];        // peer chunk totals (slot = peer cix)
    __shared__ double s_tot, s_off;

    cg::cluster_group cl = cg::this_cluster();

    int blk = blockIdx.x;              // b*CH + cix
    int b   = blk >> 3;
    int cix = blk & 7;                 // == cluster block rank
    int tid = threadIdx.x;             // 0..255
    int t   = cix * CSZ + tid;
    int len = lens[b];
    int base = b * SS;

    float a = 0.f;
    if (t < len) {
        float4 rx = g_rx[base + t];
        float logit = g_beff + rx.x + rx.y + rx.z;
        a = 1.f / (1.f + expf(-logit));
    }

    double v = (double)a;
    int lane = tid & 31, wid = tid >> 5;
#pragma unroll
    for (int off = 1; off < 32; off <<= 1) {
        double n = __shfl_up_sync(0xffffffffu, v, off);
        if (lane >= off) v += n;
    }
    if (lane == 31) wt[wid] = v;
    __syncthreads();
    if (tid == 0) {
        double run = 0.0;
#pragma unroll
        for (int w = 0; w < 8; ++w) { wo[w] = run; run += wt[w]; }
        s_tot = run;
    }
    __syncthreads();

    if (tid < CH) {                    // DSMEM broadcast of chunk total
        double* peer = cl.map_shared_rank(ctot, tid);
        peer[cix] = s_tot;
    }
    cl.sync();

    if (tid == 0) {                    // fixed-order exclusive offset
        double run = 0.0;
#pragma unroll
        for (int cc = 0; cc < CH; ++cc) {
            if (cc == cix) { s_off = run; }
            run += ctot[cc];
        }
        if (cix == CH - 1) {
            int F = (int)floor(run);
            g_F[b] = F;
            if (lens_out) lens_out[b] = (float)F;
        }
    }
    __syncthreads();

    if (t < len) {
        double Ci = s_off + wo[wid] + v;         // inclusive at t
        double Ce = Ci - (double)a;              // exclusive
        double fp = floor(Ce);
        double fc = floor(Ci);
        float w1, w2 = 0.f;
        if (fc > fp) {                           // fire (alpha<1 => fc == fp+1)
            float aaccf = (float)(Ce - fp);      // reference-style f32 aacc
            w1 = 1.0f - aaccf;
            w2 = a - w1;
            g_firepos[base + (int)fp] = t;
        } else {
            w1 = a;
        }
        g_wmain[base + t]  = w1;
        g_wspill[base + t] = w2;
    }
}

// ============================================================
// kD: JG=8 output rows per block -> contiguous t sweep, each x row
// read once; zero-fill rows batched.  grid (SS/JG, BB) x 192.
// Per-row accumulation order identical to reference (spill, mains, a1).
// ============================================================
__global__ void kD(const float* __restrict__ x, float* __restrict__ out) {
    int b  = blockIdx.y;
    int j0 = blockIdx.x * JG;
    int i  = threadIdx.x;                 // 0..191
    int F  = g_F[b];
    int base = b * SS;
    const float4* x4 = (const float4*)x + (size_t)base * DD4 + i;
    float4* o4 = (float4*)out + (size_t)(base + j0) * DD4 + i;

    int p_prev = (j0 > 0) ? g_firepos[base + j0 - 1] : -1;  // used only if j0 < F

#pragma unroll
    for (int j = j0; j < j0 + JG; ++j, o4 += DD4) {
        if (j >= F) { *o4 = make_float4(0.f, 0.f, 0.f, 0.f); continue; }

        int p1 = g_firepos[base + j];
        float4 acc = make_float4(0.f, 0.f, 0.f, 0.f);
        int t;
        if (j == 0) {
            t = 0;
        } else {
            t = p_prev;                       // spill a2*h from previous fire step
            float w = g_wspill[base + t];
            float4 h = __ldg(x4 + (size_t)t * DD4);
            acc.x = w * h.x; acc.y = w * h.y; acc.z = w * h.z; acc.w = w * h.w;
            ++t;
        }
#pragma unroll 4
        for (; t <= p1; ++t) {                // interior a*h ... then a1*h at fire
            float w = g_wmain[base + t];
            float4 h = __ldg(x4 + (size_t)t * DD4);
            acc.x += w * h.x; acc.y += w * h.y; acc.z += w * h.z; acc.w += w * h.w;
        }
        *o4 = acc;
        p_prev = p1;
    }
}

// ============================================================
extern "C" void kernel_launch(void* const* d_in, const int* in_sizes, int n_in,
                              void* d_out, int out_size) {
    const float* x      = (const float*)d_in[0];   // encoder_outputs (B,S,D)
    const int*   lens   = (const int*)  d_in[1];   // encoder_lens (B,)
    const float* conv_w = (const float*)d_in[2];   // (D,D,3)
    const float* conv_b = (const float*)d_in[3];   // (D,)
    const float* lin_w  = (const float*)d_in[4];   // (1,D)
    const float* lin_b  = (const float*)d_in[5];   // (1,)
    float* out = (float*)d_out;
    float* lens_out = (out_size >= BB * SS * DD + BB) ? out + (size_t)BB * SS * DD
                                                      : nullptr;

    kA <<<ROW3 / TPB_A, 256>>>(conv_w, conv_b, lin_w, lin_b);
    kB <<<BB * SS / 8, 256>>>(x, lens);
    kCc<<<BB * CH, 256>>>(lens, lens_out);
    kD <<<dim3(SS / JG, BB), 192>>>(x, out);
}